// round 7
// baseline (speedup 1.0000x reference)
#include <cuda_runtime.h>
#include <math.h>

// Problem constants
#define Bn   2
#define HIDn 128
#define NVn  16
#define Hn   361
#define Wn   720
#define PADn 2
#define Hpn  (Hn + 2*PADn)      // 365
#define Wpn  (Wn + 2*PADn)      // 724
#define HWn  (Hn*Wn)            // 259920
#define ACO  (-0.75f)
#define TWOPI 6.28318530717958647692f

typedef unsigned long long ull;

// Scratch (static device arrays; no runtime allocation)
__device__ float g_pad[(size_t)Bn*NVn*Hpn*Wpn];   // padded projected velocities
__device__ float g_slat[Hn];
__device__ float g_clat[Hn];

// ---- packed fp32x2 helpers ------------------------------------------------
__device__ __forceinline__ ull pk2(float a, float b) {
    ull r; asm("mov.b64 %0, {%1, %2};" : "=l"(r) : "f"(a), "f"(b)); return r;
}
__device__ __forceinline__ ull ffma2(ull a, ull b, ull c) {
    ull d; asm("fma.rn.f32x2 %0, %1, %2, %3;" : "=l"(d) : "l"(a), "l"(b), "l"(c)); return d;
}

// ---------------------------------------------------------------------------
// Kernel T: per-latitude-row sincos table (361 entries)
// ---------------------------------------------------------------------------
__global__ void kT_tables(const float* __restrict__ latg) {
    int h = blockIdx.x * blockDim.x + threadIdx.x;
    if (h < Hn) {
        float s, c;
        sincosf(latg[(size_t)h * Wn], &s, &c);
        g_slat[h] = s;
        g_clat[h] = c;
    }
}

// ---------------------------------------------------------------------------
// Kernel A: down projection (128 -> 16), 4 adjacent pixels per thread.
// One weight LDS.64 feeds two ffma2 (pixel pairs A and B).
// ---------------------------------------------------------------------------
__global__ void __launch_bounds__(256, 2)
kA_downproj(const float* __restrict__ x,
            const float* __restrict__ down_w,
            const float* __restrict__ down_b) {
    __shared__ ull s_w2[HIDn*NVn];   // [c][o], weight broadcast-packed
    __shared__ float s_b[NVn];
    for (int i = threadIdx.x; i < HIDn*NVn; i += blockDim.x) {
        int o = i % NVn, c = i / NVn;
        float wv = down_w[o*HIDn + c];
        s_w2[c*NVn + o] = pk2(wv, wv);
    }
    if (threadIdx.x < NVn) s_b[threadIdx.x] = down_b[threadIdx.x];
    __syncthreads();

    int idx = blockIdx.x * blockDim.x + threadIdx.x;   // quad index
    if (idx >= Bn*(HWn/4)) return;
    int b = idx / (HWn/4);
    int r = (idx - b*(HWn/4)) * 4;     // multiple of 4; Wn%4==0 -> same row
    int h = r / Wn;
    int w = r - h*Wn;

    ull accA[NVn], accB[NVn];
#pragma unroll
    for (int o = 0; o < NVn; o++) { accA[o] = pk2(s_b[o], s_b[o]); accB[o] = accA[o]; }

    const float* xp = x + (size_t)b*HIDn*HWn + r;
#pragma unroll 4
    for (int c = 0; c < HIDn; c++) {
        float4 xq = *reinterpret_cast<const float4*>(xp + (size_t)c*HWn);
        ull xa = pk2(xq.x, xq.y);
        ull xb = pk2(xq.z, xq.w);
        const ull* wr = s_w2 + c*NVn;
#pragma unroll
        for (int o = 0; o < NVn; o++) {
            ull wv = wr[o];
            accA[o] = ffma2(xa, wv, accA[o]);
            accB[o] = ffma2(xb, wv, accB[o]);
        }
    }
#pragma unroll
    for (int o = 0; o < NVn; o++) {
        float* dst = &g_pad[(((size_t)(b*NVn + o))*Hpn + (h + PADn))*Wpn + (w + PADn)];
        *reinterpret_cast<ull*>(dst)     = accA[o];
        *reinterpret_cast<ull*>(dst + 2) = accB[o];
    }
}

// ---------------------------------------------------------------------------
// Kernel B: pole-row fix on proj (mean over longitude, broadcast).
// ---------------------------------------------------------------------------
__global__ void kB_polefix_proj() {
    int plane = blockIdx.x >> 1;
    int which = blockIdx.x & 1;
    int hrow  = which ? (Hn - 1) : 0;
    float* row = g_pad + ((size_t)plane*Hpn + (hrow + PADn))*Wpn + PADn;

    __shared__ float s[256];
    float sum = 0.f;
    for (int w = threadIdx.x; w < Wn; w += 256) sum += row[w];
    s[threadIdx.x] = sum;
    __syncthreads();
    for (int st = 128; st > 0; st >>= 1) {
        if (threadIdx.x < st) s[threadIdx.x] += s[threadIdx.x + st];
        __syncthreads();
    }
    float mean = s[0] * (1.0f / (float)Wn);
    for (int w = threadIdx.x; w < Wn; w += 256) row[w] = mean;
}

// ---------------------------------------------------------------------------
// Kernel C: fill geo-cyclic halo — halo cells only.
// ---------------------------------------------------------------------------
#define HALO_PER_PLANE (4*Wpn + Hn*4)
__global__ void kC_halo() {
    int idx = blockIdx.x * blockDim.x + threadIdx.x;
    if (idx >= Bn*NVn*HALO_PER_PLANE) return;
    int plane = idx / HALO_PER_PLANE;
    int i = idx - plane*HALO_PER_PLANE;

    int rrow, pc;
    if (i < 2*Wpn) {                      // top 2 rows
        rrow = i / Wpn;
        pc = i - rrow*Wpn;
    } else if (i < 4*Wpn) {               // bottom 2 rows
        int j = i - 2*Wpn;
        rrow = Hpn - 2 + j / Wpn;
        pc = j - (j/Wpn)*Wpn;
    } else {                              // side columns of middle rows
        int j = i - 4*Wpn;
        rrow = PADn + (j >> 2);
        int k = j & 3;
        pc = (k < 2) ? k : (Wpn - 4 + k);
    }

    int cj;
    if (pc < PADn)            cj = Wn - PADn + pc;
    else if (pc >= PADn + Wn) cj = pc - PADn - Wn;
    else                      cj = pc - PADn;

    int sr;
    if (rrow < PADn) {
        sr = PADn - 1 - rrow;
        cj = (cj + Wn/2) % Wn;
    } else if (rrow >= PADn + Hn) {
        int t = rrow - (PADn + Hn);
        sr = Hn - 1 - t;
        cj = (cj + Wn/2) % Wn;
    } else {
        sr = rrow - PADn;
    }
    g_pad[((size_t)plane*Hpn + rrow)*Wpn + pc] =
        g_pad[((size_t)plane*Hpn + (sr + PADn))*Wpn + (cj + PADn)];
}

// ---------------------------------------------------------------------------
// small-angle sin/cos (|x| < ~0.1): abs error < 2e-9
// ---------------------------------------------------------------------------
__device__ __forceinline__ float sin_sm(float x) {
    float x2 = x*x;
    return x * fmaf(x2, fmaf(x2, 8.3333333e-3f, -1.6666667e-1f), 1.0f);
}
__device__ __forceinline__ float cos_sm(float x) {
    float x2 = x*x;
    return fmaf(x2, fmaf(x2, 4.1666667e-2f, -0.5f), 1.0f);
}

// one departure-point bicubic sample (all taps proven in-bounds)
__device__ __forceinline__ float sample_one(
        const float* __restrict__ pp, float uu, float vv, float dt,
        float slg, float clg, float lo,
        float minLat, float dLatInv, float minLon, float dLonInv) {
    float lon_pr = -uu * dt;
    float lat_pr = -vv * dt;
    float slp = sin_sm(lat_pr), clp = cos_sm(lat_pr);
    float sln = sin_sm(lon_pr), cln = cos_sm(lon_pr);

    float sin_lat = fmaf(slp, clg, clp*cln*slg);
    sin_lat = fminf(fmaxf(sin_lat, -1.0f + 1e-7f), 1.0f - 1e-7f);
    float lat_dep = asinf(sin_lat);
    float num = clp * sln;
    float den = clp*cln*clg - slp*slg;
    float lon_dep = lo + atan2f(num, den);
    float a = lon_dep + TWOPI;
    lon_dep = a - floorf(a * (1.0f/TWOPI)) * TWOPI;   // remainder(a, 2pi)

    float pix_x = (lon_dep - minLon) * dLonInv * (float)(Wn - 1);
    float pix_y = (lat_dep - minLat) * dLatInv * (float)(Hn - 1);
    // normalize/unnormalize round trip (align_corners=True), matches reference fp path
    float gx = 2.0f*((pix_x + (float)PADn)/(float)(Wpn - 1)) - 1.0f;
    float gy = 2.0f*((pix_y + (float)PADn)/(float)(Hpn - 1)) - 1.0f;
    float ix = (gx + 1.0f)*0.5f*(float)(Wpn - 1);
    float iy = (gy + 1.0f)*0.5f*(float)(Hpn - 1);

    float x0f = floorf(ix), y0f = floorf(iy);
    float tx = ix - x0f, ty = iy - y0f;
    int x0 = (int)x0f, y0 = (int)y0f;

    float wx0, wx1, wx2, wx3, wy0, wy1, wy2, wy3;
    {
        float t = tx, t1 = t + 1.0f, t2 = 1.0f - t, t3 = 2.0f - t;
        wx0 = ((ACO*t1 - 5.0f*ACO)*t1 + 8.0f*ACO)*t1 - 4.0f*ACO;
        wx1 = ((ACO + 2.0f)*t - (ACO + 3.0f))*t*t + 1.0f;
        wx2 = ((ACO + 2.0f)*t2 - (ACO + 3.0f))*t2*t2 + 1.0f;
        wx3 = ((ACO*t3 - 5.0f*ACO)*t3 + 8.0f*ACO)*t3 - 4.0f*ACO;
    }
    {
        float t = ty, t1 = t + 1.0f, t2 = 1.0f - t, t3 = 2.0f - t;
        wy0 = ((ACO*t1 - 5.0f*ACO)*t1 + 8.0f*ACO)*t1 - 4.0f*ACO;
        wy1 = ((ACO + 2.0f)*t - (ACO + 3.0f))*t*t + 1.0f;
        wy2 = ((ACO + 2.0f)*t2 - (ACO + 3.0f))*t2*t2 + 1.0f;
        wy3 = ((ACO*t3 - 5.0f*ACO)*t3 + 8.0f*ACO)*t3 - 4.0f*ACO;
    }

    const float* rp = pp + (size_t)(y0-1)*Wpn + (x0-1);
    float r0 = fmaf(rp[3], wx3, fmaf(rp[2], wx2, fmaf(rp[1], wx1, rp[0]*wx0)));
    rp += Wpn;
    float r1 = fmaf(rp[3], wx3, fmaf(rp[2], wx2, fmaf(rp[1], wx1, rp[0]*wx0)));
    rp += Wpn;
    float r2 = fmaf(rp[3], wx3, fmaf(rp[2], wx2, fmaf(rp[1], wx1, rp[0]*wx0)));
    rp += Wpn;
    float r3 = fmaf(rp[3], wx3, fmaf(rp[2], wx2, fmaf(rp[1], wx1, rp[0]*wx0)));
    return fmaf(r3, wy3, fmaf(r2, wy2, fmaf(r1, wy1, r0*wy0)));
}

// ---------------------------------------------------------------------------
// Kernel F (fused D1+D2): per pixel-QUAD, 64 departure-point samples (16 v x 4
// px), depthwise scale, then 16->128 up projection with one weight LDS per
// two ffma2; STG.128 output.
// ---------------------------------------------------------------------------
__global__ void __launch_bounds__(256, 2)
kF_sample_upproj(const float* __restrict__ U,
                 const float* __restrict__ Vf,
                 const float* __restrict__ dtp,
                 const float* __restrict__ latg,
                 const float* __restrict__ lonp,
                 const float* __restrict__ dww,
                 const float* __restrict__ dwb,
                 const float* __restrict__ upw,
                 const float* __restrict__ upb,
                 float* __restrict__ out) {
    __shared__ ull s_w2[HIDn*NVn];   // [o][v], broadcast-packed up_w
    __shared__ float s_b[HIDn];
    __shared__ float s_dw[NVn], s_db[NVn];
    for (int i = threadIdx.x; i < HIDn*NVn; i += blockDim.x) {
        float wv = upw[i];
        s_w2[i] = pk2(wv, wv);
    }
    for (int i = threadIdx.x; i < HIDn; i += blockDim.x) s_b[i] = upb[i];
    if (threadIdx.x < NVn) {
        s_dw[threadIdx.x] = dww[threadIdx.x];
        s_db[threadIdx.x] = dwb[threadIdx.x];
    }
    __syncthreads();

    int idx = blockIdx.x * blockDim.x + threadIdx.x;   // quad index
    if (idx >= Bn*(HWn/4)) return;
    int b = idx / (HWn/4);
    int r = (idx - b*(HWn/4)) * 4;     // quad-aligned pixel index
    int h = r / Wn;
    int w = r - h*Wn;

    float dt = __ldg(dtp);
    float minLat = __ldg(latg);
    float maxLat = __ldg(latg + (size_t)(Hn-1)*Wn);
    float minLon = __ldg(lonp);
    float maxLon = __ldg(lonp + (Wn-1));
    float dLatInv = 1.0f / (maxLat - minLat);
    float dLonInv = 1.0f / (maxLon - minLon);

    float slg = g_slat[h];
    float clg = g_clat[h];
    float lo0 = __ldg(lonp + w);
    float lo1 = __ldg(lonp + w + 1);
    float lo2 = __ldg(lonp + w + 2);
    float lo3 = __ldg(lonp + w + 3);

    ull yvA[NVn], yvB[NVn];
#pragma unroll
    for (int v = 0; v < NVn; v++) {
        int plane = b*NVn + v;
        size_t base = (size_t)plane*HWn + r;
        float4 uq = *reinterpret_cast<const float4*>(U + base);
        float4 vq = *reinterpret_cast<const float4*>(Vf + base);
        const float* pp = g_pad + (size_t)plane*Hpn*Wpn;
        float a0 = sample_one(pp, uq.x, vq.x, dt, slg, clg, lo0,
                              minLat, dLatInv, minLon, dLonInv);
        float a1 = sample_one(pp, uq.y, vq.y, dt, slg, clg, lo1,
                              minLat, dLatInv, minLon, dLonInv);
        float a2 = sample_one(pp, uq.z, vq.z, dt, slg, clg, lo2,
                              minLat, dLatInv, minLon, dLonInv);
        float a3 = sample_one(pp, uq.w, vq.w, dt, slg, clg, lo3,
                              minLat, dLatInv, minLon, dLonInv);
        float dwv = s_dw[v], dbv = s_db[v];
        yvA[v] = pk2(fmaf(a0, dwv, dbv), fmaf(a1, dwv, dbv));
        yvB[v] = pk2(fmaf(a2, dwv, dbv), fmaf(a3, dwv, dbv));
    }

    float* op = out + (size_t)b*HIDn*HWn + r;
#pragma unroll 4
    for (int o = 0; o < HIDn; o++) {
        ull accA = pk2(s_b[o], s_b[o]);
        ull accB = accA;
        const ull* wr = s_w2 + o*NVn;
#pragma unroll
        for (int vq2 = 0; vq2 < NVn; vq2++) {
            ull wv = wr[vq2];
            accA = ffma2(yvA[vq2], wv, accA);
            accB = ffma2(yvB[vq2], wv, accB);
        }
        ulonglong2 pairout;
        pairout.x = accA; pairout.y = accB;
        *reinterpret_cast<ulonglong2*>(op + (size_t)o*HWn) = pairout;
    }
}

// ---------------------------------------------------------------------------
// Kernel E: pole-row fix on output.
// ---------------------------------------------------------------------------
__global__ void kE_polefix_out(float* __restrict__ out) {
    int bo = blockIdx.x >> 1;
    int which = blockIdx.x & 1;
    float* row = out + (size_t)bo*HWn + (which ? (size_t)(Hn-1)*Wn : 0);

    __shared__ float s[256];
    float sum = 0.f;
    for (int w = threadIdx.x; w < Wn; w += 256) sum += row[w];
    s[threadIdx.x] = sum;
    __syncthreads();
    for (int st = 128; st > 0; st >>= 1) {
        if (threadIdx.x < st) s[threadIdx.x] += s[threadIdx.x + st];
        __syncthreads();
    }
    float mean = s[0] * (1.0f / (float)Wn);
    for (int w = threadIdx.x; w < Wn; w += 256) row[w] = mean;
}

// ---------------------------------------------------------------------------
extern "C" void kernel_launch(void* const* d_in, const int* in_sizes, int n_in,
                              void* d_out, int out_size) {
    const float* hidden = (const float*)d_in[0];
    const float* U      = (const float*)d_in[1];
    const float* V      = (const float*)d_in[2];
    const float* dt     = (const float*)d_in[3];
    const float* latg   = (const float*)d_in[4];
    const float* lonog  = (const float*)d_in[5];
    const float* down_w = (const float*)d_in[6];
    const float* down_b = (const float*)d_in[7];
    const float* dw_w   = (const float*)d_in[8];
    const float* dw_b   = (const float*)d_in[9];
    const float* up_w   = (const float*)d_in[10];
    const float* up_b   = (const float*)d_in[11];
    float* out = (float*)d_out;

    kT_tables<<<2, 256>>>(latg);

    int nQuads = Bn*(HWn/4);                 // 129,960
    kA_downproj<<<(nQuads + 255)/256, 256>>>(hidden, down_w, down_b);
    kB_polefix_proj<<<Bn*NVn*2, 256>>>();
    int nHalo = Bn*NVn*HALO_PER_PLANE;       // 138,880
    kC_halo<<<(nHalo + 255)/256, 256>>>();
    kF_sample_upproj<<<(nQuads + 255)/256, 256>>>(U, V, dt, latg, lonog,
                                                  dw_w, dw_b, up_w, up_b, out);
    kE_polefix_out<<<Bn*HIDn*2, 256>>>(out);
}

// round 8
// speedup vs baseline: 1.0789x; 1.0789x over previous
#include <cuda_runtime.h>
#include <math.h>

// Problem constants
#define Bn   2
#define HIDn 128
#define NVn  16
#define Hn   361
#define Wn   720
#define PADn 2
#define Hpn  (Hn + 2*PADn)      // 365
#define Wpn  (Wn + 2*PADn)      // 724
#define HWn  (Hn*Wn)            // 259920
#define ACO  (-0.75f)
#define TWOPI 6.28318530717958647692f
#define PIf  3.14159265358979323f
#define PIO2 1.5707963267948966f
#define PIO4 0.78539816339744831f

typedef unsigned long long ull;

// Scratch (static device arrays; no runtime allocation)
__device__ float g_pad[(size_t)Bn*NVn*Hpn*Wpn];   // padded projected velocities
__device__ float g_slat[Hn];
__device__ float g_clat[Hn];

// ---- packed fp32x2 helpers ------------------------------------------------
__device__ __forceinline__ ull pk2(float a, float b) {
    ull r; asm("mov.b64 %0, {%1, %2};" : "=l"(r) : "f"(a), "f"(b)); return r;
}
__device__ __forceinline__ ull ffma2(ull a, ull b, ull c) {
    ull d; asm("fma.rn.f32x2 %0, %1, %2, %3;" : "=l"(d) : "l"(a), "l"(b), "l"(c)); return d;
}

// ---------------------------------------------------------------------------
// Kernel A: down projection (128 -> 16), 2 adjacent pixels per thread via
// packed fp32x2 FMA. Writes into padded interior. (R4 version — best.)
// ---------------------------------------------------------------------------
__global__ void kA_downproj(const float* __restrict__ x,
                            const float* __restrict__ down_w,
                            const float* __restrict__ down_b) {
    __shared__ ull s_w2[HIDn*NVn];   // [c][o], weight broadcast-packed
    __shared__ float s_b[NVn];
    for (int i = threadIdx.x; i < HIDn*NVn; i += blockDim.x) {
        int o = i % NVn, c = i / NVn;
        float wv = down_w[o*HIDn + c];
        s_w2[c*NVn + o] = pk2(wv, wv);
    }
    if (threadIdx.x < NVn) s_b[threadIdx.x] = down_b[threadIdx.x];
    __syncthreads();

    int idx = blockIdx.x * blockDim.x + threadIdx.x;   // pair index
    if (idx >= Bn*(HWn/2)) return;
    int b = idx / (HWn/2);
    int r = (idx - b*(HWn/2)) * 2;     // even; pairs never straddle rows (Wn even)
    int h = r / Wn;
    int w = r - h*Wn;

    ull acc[NVn];
#pragma unroll
    for (int o = 0; o < NVn; o++) acc[o] = pk2(s_b[o], s_b[o]);

    const float* xp = x + (size_t)b*HIDn*HWn + r;
#pragma unroll 4
    for (int c = 0; c < HIDn; c++) {
        ull xv = *reinterpret_cast<const ull*>(xp + (size_t)c*HWn);
        const ull* wr = s_w2 + c*NVn;
#pragma unroll
        for (int o = 0; o < NVn; o++) acc[o] = ffma2(xv, wr[o], acc[o]);
    }
#pragma unroll
    for (int o = 0; o < NVn; o++) {
        *reinterpret_cast<ull*>(
            &g_pad[(((size_t)(b*NVn + o))*Hpn + (h + PADn))*Wpn + (w + PADn)]) = acc[o];
    }
}

// ---------------------------------------------------------------------------
// Kernel P: pole rows + sincos tables.
// 4 blocks = (b, pole). Pole-fixed proj row = down-proj of the hidden-row
// longitude mean (linear => identical to mean of proj row). Also fills
// g_slat/g_clat (block 0).
// ---------------------------------------------------------------------------
__global__ void kP_pole_tables(const float* __restrict__ x,
                               const float* __restrict__ down_w,
                               const float* __restrict__ down_b,
                               const float* __restrict__ latg) {
    __shared__ float s_sum[256];
    __shared__ float s_mean[HIDn];
    __shared__ float s_val[NVn];
    int b = blockIdx.x >> 1;
    int pole = blockIdx.x & 1;
    int hrow = pole ? (Hn - 1) : 0;

    if (blockIdx.x == 0) {
        for (int h = threadIdx.x; h < Hn; h += 256) {
            float s, c;
            sincosf(latg[(size_t)h * Wn], &s, &c);
            g_slat[h] = s;
            g_clat[h] = c;
        }
    }

    int c = threadIdx.x >> 1;
    int half = threadIdx.x & 1;
    const float* rowp = x + ((size_t)b*HIDn + c)*HWn + (size_t)hrow*Wn + half*(Wn/2);
    float sum = 0.f;
    for (int w = 0; w < Wn/2; w++) sum += rowp[w];
    s_sum[threadIdx.x] = sum;
    __syncthreads();
    if (half == 0)
        s_mean[c] = (s_sum[threadIdx.x] + s_sum[threadIdx.x + 1]) * (1.0f/(float)Wn);
    __syncthreads();

    if (threadIdx.x < NVn) {
        int o = threadIdx.x;
        float acc = down_b[o];
        for (int cc = 0; cc < HIDn; cc++)
            acc = fmaf(s_mean[cc], down_w[o*HIDn + cc], acc);
        s_val[o] = acc;
    }
    __syncthreads();

    for (int i = threadIdx.x; i < NVn*Wn; i += 256) {
        int o = i / Wn;
        int w = i - o*Wn;
        g_pad[(((size_t)(b*NVn + o))*Hpn + (hrow + PADn))*Wpn + (w + PADn)] = s_val[o];
    }
}

// ---------------------------------------------------------------------------
// Kernel C: fill geo-cyclic halo — halo cells only.
// ---------------------------------------------------------------------------
#define HALO_PER_PLANE (4*Wpn + Hn*4)
__global__ void kC_halo() {
    int idx = blockIdx.x * blockDim.x + threadIdx.x;
    if (idx >= Bn*NVn*HALO_PER_PLANE) return;
    int plane = idx / HALO_PER_PLANE;
    int i = idx - plane*HALO_PER_PLANE;

    int rrow, pc;
    if (i < 2*Wpn) {                      // top 2 rows
        rrow = i / Wpn;
        pc = i - rrow*Wpn;
    } else if (i < 4*Wpn) {               // bottom 2 rows
        int j = i - 2*Wpn;
        rrow = Hpn - 2 + j / Wpn;
        pc = j - (j/Wpn)*Wpn;
    } else {                              // side columns of middle rows
        int j = i - 4*Wpn;
        rrow = PADn + (j >> 2);
        int k = j & 3;
        pc = (k < 2) ? k : (Wpn - 4 + k);
    }

    int cj;
    if (pc < PADn)            cj = Wn - PADn + pc;
    else if (pc >= PADn + Wn) cj = pc - PADn - Wn;
    else                      cj = pc - PADn;

    int sr;
    if (rrow < PADn) {
        sr = PADn - 1 - rrow;
        cj = (cj + Wn/2) % Wn;
    } else if (rrow >= PADn + Hn) {
        int t = rrow - (PADn + Hn);
        sr = Hn - 1 - t;
        cj = (cj + Wn/2) % Wn;
    } else {
        sr = rrow - PADn;
    }
    g_pad[((size_t)plane*Hpn + rrow)*Wpn + pc] =
        g_pad[((size_t)plane*Hpn + (sr + PADn))*Wpn + (cj + PADn)];
}

// ---------------------------------------------------------------------------
// fast transcendentals
// ---------------------------------------------------------------------------
__device__ __forceinline__ float sin_sm(float x) {        // |x| < ~0.1
    float x2 = x*x;
    return x * fmaf(x2, fmaf(x2, 8.3333333e-3f, -1.6666667e-1f), 1.0f);
}
__device__ __forceinline__ float cos_sm(float x) {
    float x2 = x*x;
    return fmaf(x2, fmaf(x2, 4.1666667e-2f, -0.5f), 1.0f);
}

// branchless atan2, err ~1e-7 rad (Cephes-style poly + conditional reduction)
__device__ __forceinline__ float fast_atan2(float y, float x) {
    float ax = fabsf(x), ay = fabsf(y);
    float hi = fmaxf(ax, ay), lo = fminf(ax, ay);
    float t = __fdividef(lo, hi);              // [0,1]
    bool red = t > 0.41421356f;
    float xr = __fdividef(t - 1.0f, t + 1.0f);
    float p = red ? xr : t;
    float z = p * p;
    float poly = fmaf(fmaf(fmaf(fmaf(z, 8.05374449538e-2f, -1.38776856032e-1f), z,
                 1.99777106478e-1f), z, -3.33329491539e-1f), z * p, p);
    float r = red ? (poly + PIO4) : poly;
    r = (ay > ax) ? (PIO2 - r) : r;
    r = (x < 0.0f) ? (PIf - r) : r;
    return copysignf(r, y);
}

// branchless asin, err ~1e-6 rad
__device__ __forceinline__ float fast_asin(float x) {
    float a = fabsf(x);
    bool big = a > 0.5f;
    float zb = 0.5f * (1.0f - a);
    float z = big ? zb : a*a;
    float arg = big ? sqrtf(zb) : a;
    float p = arg * fmaf(z, fmaf(z, fmaf(z, fmaf(z, fmaf(z, fmaf(z,
              1.7352764e-2f, 2.2372159e-2f), 3.0381944e-2f), 4.4642857e-2f),
              7.5e-2f), 1.6666667e-1f), 1.0f);
    float r = big ? fmaf(-2.0f, p, PIO2) : p;
    return copysignf(r, x);
}

// one departure-point bicubic sample (all taps proven in-bounds)
__device__ __forceinline__ float sample_one(
        const float* __restrict__ pp, float uu, float vv, float dt,
        float slg, float clg, float lo,
        float minLat, float dLatInv, float minLon, float dLonInv) {
    float lon_pr = -uu * dt;
    float lat_pr = -vv * dt;
    float slp = sin_sm(lat_pr), clp = cos_sm(lat_pr);
    float sln = sin_sm(lon_pr), cln = cos_sm(lon_pr);

    float sin_lat = fmaf(slp, clg, clp*cln*slg);
    sin_lat = fminf(fmaxf(sin_lat, -1.0f + 1e-7f), 1.0f - 1e-7f);
    float lat_dep = fast_asin(sin_lat);
    float num = clp * sln;
    float den = clp*cln*clg - slp*slg;
    float lon_dep = lo + fast_atan2(num, den);
    float a = lon_dep + TWOPI;
    lon_dep = a - floorf(a * (1.0f/TWOPI)) * TWOPI;   // remainder(a, 2pi)

    float pix_x = (lon_dep - minLon) * dLonInv * (float)(Wn - 1);
    float pix_y = (lat_dep - minLat) * dLatInv * (float)(Hn - 1);
    // normalize/unnormalize round trip (align_corners=True), matches reference fp path
    float gx = 2.0f*((pix_x + (float)PADn)/(float)(Wpn - 1)) - 1.0f;
    float gy = 2.0f*((pix_y + (float)PADn)/(float)(Hpn - 1)) - 1.0f;
    float ix = (gx + 1.0f)*0.5f*(float)(Wpn - 1);
    float iy = (gy + 1.0f)*0.5f*(float)(Hpn - 1);

    float x0f = floorf(ix), y0f = floorf(iy);
    float tx = ix - x0f, ty = iy - y0f;
    int x0 = (int)x0f, y0 = (int)y0f;

    float wx0, wx1, wx2, wx3, wy0, wy1, wy2, wy3;
    {
        float t = tx, t1 = t + 1.0f, t2 = 1.0f - t, t3 = 2.0f - t;
        wx0 = ((ACO*t1 - 5.0f*ACO)*t1 + 8.0f*ACO)*t1 - 4.0f*ACO;
        wx1 = ((ACO + 2.0f)*t - (ACO + 3.0f))*t*t + 1.0f;
        wx2 = ((ACO + 2.0f)*t2 - (ACO + 3.0f))*t2*t2 + 1.0f;
        wx3 = ((ACO*t3 - 5.0f*ACO)*t3 + 8.0f*ACO)*t3 - 4.0f*ACO;
    }
    {
        float t = ty, t1 = t + 1.0f, t2 = 1.0f - t, t3 = 2.0f - t;
        wy0 = ((ACO*t1 - 5.0f*ACO)*t1 + 8.0f*ACO)*t1 - 4.0f*ACO;
        wy1 = ((ACO + 2.0f)*t - (ACO + 3.0f))*t*t + 1.0f;
        wy2 = ((ACO + 2.0f)*t2 - (ACO + 3.0f))*t2*t2 + 1.0f;
        wy3 = ((ACO*t3 - 5.0f*ACO)*t3 + 8.0f*ACO)*t3 - 4.0f*ACO;
    }

    const float* rp = pp + (size_t)(y0-1)*Wpn + (x0-1);
    float r0 = fmaf(rp[3], wx3, fmaf(rp[2], wx2, fmaf(rp[1], wx1, rp[0]*wx0)));
    rp += Wpn;
    float r1 = fmaf(rp[3], wx3, fmaf(rp[2], wx2, fmaf(rp[1], wx1, rp[0]*wx0)));
    rp += Wpn;
    float r2 = fmaf(rp[3], wx3, fmaf(rp[2], wx2, fmaf(rp[1], wx1, rp[0]*wx0)));
    rp += Wpn;
    float r3 = fmaf(rp[3], wx3, fmaf(rp[2], wx2, fmaf(rp[1], wx1, rp[0]*wx0)));
    return fmaf(r3, wy3, fmaf(r2, wy2, fmaf(r1, wy1, r0*wy0)));
}

// ---------------------------------------------------------------------------
// Kernel F (fused D1+D2): per pixel-PAIR, 32 departure-point samples,
// depthwise scale, 16->128 up projection, write out. (R4 version + fast
// transcendentals.)
// ---------------------------------------------------------------------------
__global__ void __launch_bounds__(256, 2)
kF_sample_upproj(const float* __restrict__ U,
                 const float* __restrict__ Vf,
                 const float* __restrict__ dtp,
                 const float* __restrict__ latg,
                 const float* __restrict__ lonp,
                 const float* __restrict__ dww,
                 const float* __restrict__ dwb,
                 const float* __restrict__ upw,
                 const float* __restrict__ upb,
                 float* __restrict__ out) {
    __shared__ ull s_w2[HIDn*NVn];   // [o][v], broadcast-packed up_w
    __shared__ float s_b[HIDn];
    __shared__ float s_dw[NVn], s_db[NVn];
    for (int i = threadIdx.x; i < HIDn*NVn; i += blockDim.x) {
        float wv = upw[i];
        s_w2[i] = pk2(wv, wv);
    }
    for (int i = threadIdx.x; i < HIDn; i += blockDim.x) s_b[i] = upb[i];
    if (threadIdx.x < NVn) {
        s_dw[threadIdx.x] = dww[threadIdx.x];
        s_db[threadIdx.x] = dwb[threadIdx.x];
    }
    __syncthreads();

    int idx = blockIdx.x * blockDim.x + threadIdx.x;   // pair index
    if (idx >= Bn*(HWn/2)) return;
    int b = idx / (HWn/2);
    int r = (idx - b*(HWn/2)) * 2;     // even pixel index within batch
    int h = r / Wn;
    int w = r - h*Wn;

    float dt = __ldg(dtp);
    float minLat = __ldg(latg);
    float maxLat = __ldg(latg + (size_t)(Hn-1)*Wn);
    float minLon = __ldg(lonp);
    float maxLon = __ldg(lonp + (Wn-1));
    float dLatInv = 1.0f / (maxLat - minLat);
    float dLonInv = 1.0f / (maxLon - minLon);

    float slg = g_slat[h];
    float clg = g_clat[h];
    float lo0 = __ldg(lonp + w);
    float lo1 = __ldg(lonp + w + 1);

    ull yv[NVn];
#pragma unroll
    for (int v = 0; v < NVn; v++) {
        int plane = b*NVn + v;
        size_t base = (size_t)plane*HWn + r;
        float2 up = *reinterpret_cast<const float2*>(U + base);
        float2 vp = *reinterpret_cast<const float2*>(Vf + base);
        const float* pp = g_pad + (size_t)plane*Hpn*Wpn;
        float a0 = sample_one(pp, up.x, vp.x, dt, slg, clg, lo0,
                              minLat, dLatInv, minLon, dLonInv);
        float a1 = sample_one(pp, up.y, vp.y, dt, slg, clg, lo1,
                              minLat, dLatInv, minLon, dLonInv);
        float dwv = s_dw[v], dbv = s_db[v];
        yv[v] = pk2(fmaf(a0, dwv, dbv), fmaf(a1, dwv, dbv));
    }

    float* op = out + (size_t)b*HIDn*HWn + r;
#pragma unroll 8
    for (int o = 0; o < HIDn; o++) {
        ull acc = pk2(s_b[o], s_b[o]);
        const ull* wr = s_w2 + o*NVn;
#pragma unroll
        for (int vq = 0; vq < NVn; vq++) acc = ffma2(yv[vq], wr[vq], acc);
        *reinterpret_cast<ull*>(op + (size_t)o*HWn) = acc;
    }
}

// ---------------------------------------------------------------------------
// Kernel E: pole-row fix on output.
// ---------------------------------------------------------------------------
__global__ void kE_polefix_out(float* __restrict__ out) {
    int bo = blockIdx.x >> 1;
    int which = blockIdx.x & 1;
    float* row = out + (size_t)bo*HWn + (which ? (size_t)(Hn-1)*Wn : 0);

    __shared__ float s[256];
    float sum = 0.f;
    for (int w = threadIdx.x; w < Wn; w += 256) sum += row[w];
    s[threadIdx.x] = sum;
    __syncthreads();
    for (int st = 128; st > 0; st >>= 1) {
        if (threadIdx.x < st) s[threadIdx.x] += s[threadIdx.x + st];
        __syncthreads();
    }
    float mean = s[0] * (1.0f / (float)Wn);
    for (int w = threadIdx.x; w < Wn; w += 256) row[w] = mean;
}

// ---------------------------------------------------------------------------
extern "C" void kernel_launch(void* const* d_in, const int* in_sizes, int n_in,
                              void* d_out, int out_size) {
    const float* hidden = (const float*)d_in[0];
    const float* U      = (const float*)d_in[1];
    const float* V      = (const float*)d_in[2];
    const float* dt     = (const float*)d_in[3];
    const float* latg   = (const float*)d_in[4];
    const float* lonog  = (const float*)d_in[5];
    const float* down_w = (const float*)d_in[6];
    const float* down_b = (const float*)d_in[7];
    const float* dw_w   = (const float*)d_in[8];
    const float* dw_b   = (const float*)d_in[9];
    const float* up_w   = (const float*)d_in[10];
    const float* up_b   = (const float*)d_in[11];
    float* out = (float*)d_out;

    int nPairs = Bn*(HWn/2);                 // 259920
    kA_downproj<<<(nPairs + 255)/256, 256>>>(hidden, down_w, down_b);   // 0
    kP_pole_tables<<<4, 256>>>(hidden, down_w, down_b, latg);           // 1
    int nHalo = Bn*NVn*HALO_PER_PLANE;       // 138,880
    kC_halo<<<(nHalo + 255)/256, 256>>>();                              // 2
    kF_sample_upproj<<<(nPairs + 255)/256, 256>>>(U, V, dt, latg, lonog,
                                                  dw_w, dw_b, up_w, up_b, out); // 3
    kE_polefix_out<<<Bn*HIDn*2, 256>>>(out);                            // 4
}

// round 11
// speedup vs baseline: 1.1480x; 1.0640x over previous
#include <cuda_runtime.h>
#include <math.h>

// Problem constants
#define Bn   2
#define HIDn 128
#define NVn  16
#define Hn   361
#define Wn   720
#define PADn 2
#define Hpn  (Hn + 2*PADn)      // 365
#define Wpn  (Wn + 2*PADn)      // 724
#define HWn  (Hn*Wn)            // 259920
#define ACO  (-0.75f)
#define TWOPI 6.28318530717958647692f
#define PIf  3.14159265358979323f
#define PIO2 1.5707963267948966f
#define PIO4 0.78539816339744831f

typedef unsigned long long ull;

// Scratch (static device arrays; no runtime allocation)
__device__ float g_pad[(size_t)Bn*NVn*Hpn*Wpn];   // padded projected velocities
__device__ float g_y[(size_t)Bn*NVn*HWn];         // interp * dw_w + dw_b
__device__ float g_slat[Hn];
__device__ float g_clat[Hn];

// ---- packed fp32x2 helpers ------------------------------------------------
__device__ __forceinline__ ull pk2(float a, float b) {
    ull r; asm("mov.b64 %0, {%1, %2};" : "=l"(r) : "f"(a), "f"(b)); return r;
}
__device__ __forceinline__ ull ffma2(ull a, ull b, ull c) {
    ull d; asm("fma.rn.f32x2 %0, %1, %2, %3;" : "=l"(d) : "l"(a), "l"(b), "l"(c)); return d;
}

// ---------------------------------------------------------------------------
// Kernel A: down projection (128 -> 16), 2 adjacent pixels per thread via
// packed fp32x2 FMA, c-loop unrolled 16 for MLP. Writes into padded interior.
// ---------------------------------------------------------------------------
__global__ void kA_downproj(const float* __restrict__ x,
                            const float* __restrict__ down_w,
                            const float* __restrict__ down_b) {
    __shared__ ull s_w2[HIDn*NVn];   // [c][o], weight broadcast-packed
    __shared__ float s_b[NVn];
    for (int i = threadIdx.x; i < HIDn*NVn; i += blockDim.x) {
        int o = i % NVn, c = i / NVn;
        float wv = down_w[o*HIDn + c];
        s_w2[c*NVn + o] = pk2(wv, wv);
    }
    if (threadIdx.x < NVn) s_b[threadIdx.x] = down_b[threadIdx.x];
    __syncthreads();

    int idx = blockIdx.x * blockDim.x + threadIdx.x;   // pair index
    if (idx >= Bn*(HWn/2)) return;
    int b = idx / (HWn/2);
    int r = (idx - b*(HWn/2)) * 2;     // even; pairs never straddle rows (Wn even)
    int h = r / Wn;
    int w = r - h*Wn;

    ull acc[NVn];
#pragma unroll
    for (int o = 0; o < NVn; o++) acc[o] = pk2(s_b[o], s_b[o]);

    const float* xp = x + (size_t)b*HIDn*HWn + r;
    // chunked: load 16 x-values first (16 LDG.64 in flight), then FMA
#pragma unroll 1
    for (int c0 = 0; c0 < HIDn; c0 += 16) {
        ull xv[16];
#pragma unroll
        for (int j = 0; j < 16; j++)
            xv[j] = *reinterpret_cast<const ull*>(xp + (size_t)(c0 + j)*HWn);
#pragma unroll
        for (int j = 0; j < 16; j++) {
            const ull* wr = s_w2 + (c0 + j)*NVn;
#pragma unroll
            for (int o = 0; o < NVn; o++) acc[o] = ffma2(xv[j], wr[o], acc[o]);
        }
    }
#pragma unroll
    for (int o = 0; o < NVn; o++) {
        *reinterpret_cast<ull*>(
            &g_pad[(((size_t)(b*NVn + o))*Hpn + (h + PADn))*Wpn + (w + PADn)]) = acc[o];
    }
}

// ---------------------------------------------------------------------------
// Kernel P: pole rows + sincos tables.
// 4 blocks = (b, pole). Pole-fixed proj row = down-proj of the hidden-row
// longitude mean (linear => identical to mean of proj row). Also fills
// g_slat/g_clat (block 0).
// ---------------------------------------------------------------------------
__global__ void kP_pole_tables(const float* __restrict__ x,
                               const float* __restrict__ down_w,
                               const float* __restrict__ down_b,
                               const float* __restrict__ latg) {
    __shared__ float s_sum[256];
    __shared__ float s_mean[HIDn];
    __shared__ float s_val[NVn];
    int b = blockIdx.x >> 1;
    int pole = blockIdx.x & 1;
    int hrow = pole ? (Hn - 1) : 0;

    if (blockIdx.x == 0) {
        for (int h = threadIdx.x; h < Hn; h += 256) {
            float s, c;
            sincosf(latg[(size_t)h * Wn], &s, &c);
            g_slat[h] = s;
            g_clat[h] = c;
        }
    }

    int c = threadIdx.x >> 1;
    int half = threadIdx.x & 1;
    const float* rowp = x + ((size_t)b*HIDn + c)*HWn + (size_t)hrow*Wn + half*(Wn/2);
    float sum = 0.f;
    for (int w = 0; w < Wn/2; w++) sum += rowp[w];
    s_sum[threadIdx.x] = sum;
    __syncthreads();
    if (half == 0)
        s_mean[c] = (s_sum[threadIdx.x] + s_sum[threadIdx.x + 1]) * (1.0f/(float)Wn);
    __syncthreads();

    if (threadIdx.x < NVn) {
        int o = threadIdx.x;
        float acc = down_b[o];
        for (int cc = 0; cc < HIDn; cc++)
            acc = fmaf(s_mean[cc], down_w[o*HIDn + cc], acc);
        s_val[o] = acc;
    }
    __syncthreads();

    for (int i = threadIdx.x; i < NVn*Wn; i += 256) {
        int o = i / Wn;
        int w = i - o*Wn;
        g_pad[(((size_t)(b*NVn + o))*Hpn + (hrow + PADn))*Wpn + (w + PADn)] = s_val[o];
    }
}

// ---------------------------------------------------------------------------
// Kernel C: fill geo-cyclic halo — halo cells only.
// ---------------------------------------------------------------------------
#define HALO_PER_PLANE (4*Wpn + Hn*4)
__global__ void kC_halo() {
    int idx = blockIdx.x * blockDim.x + threadIdx.x;
    if (idx >= Bn*NVn*HALO_PER_PLANE) return;
    int plane = idx / HALO_PER_PLANE;
    int i = idx - plane*HALO_PER_PLANE;

    int rrow, pc;
    if (i < 2*Wpn) {                      // top 2 rows
        rrow = i / Wpn;
        pc = i - rrow*Wpn;
    } else if (i < 4*Wpn) {               // bottom 2 rows
        int j = i - 2*Wpn;
        rrow = Hpn - 2 + j / Wpn;
        pc = j - (j/Wpn)*Wpn;
    } else {                              // side columns of middle rows
        int j = i - 4*Wpn;
        rrow = PADn + (j >> 2);
        int k = j & 3;
        pc = (k < 2) ? k : (Wpn - 4 + k);
    }

    int cj;
    if (pc < PADn)            cj = Wn - PADn + pc;
    else if (pc >= PADn + Wn) cj = pc - PADn - Wn;
    else                      cj = pc - PADn;

    int sr;
    if (rrow < PADn) {
        sr = PADn - 1 - rrow;
        cj = (cj + Wn/2) % Wn;
    } else if (rrow >= PADn + Hn) {
        int t = rrow - (PADn + Hn);
        sr = Hn - 1 - t;
        cj = (cj + Wn/2) % Wn;
    } else {
        sr = rrow - PADn;
    }
    g_pad[((size_t)plane*Hpn + rrow)*Wpn + pc] =
        g_pad[((size_t)plane*Hpn + (sr + PADn))*Wpn + (cj + PADn)];
}

// ---------------------------------------------------------------------------
// fast transcendentals
// ---------------------------------------------------------------------------
__device__ __forceinline__ float sin_sm(float x) {        // |x| < ~0.1
    float x2 = x*x;
    return x * fmaf(x2, fmaf(x2, 8.3333333e-3f, -1.6666667e-1f), 1.0f);
}
__device__ __forceinline__ float cos_sm(float x) {
    float x2 = x*x;
    return fmaf(x2, fmaf(x2, 4.1666667e-2f, -0.5f), 1.0f);
}

// branchless atan2, err ~1e-7 rad
__device__ __forceinline__ float fast_atan2(float y, float x) {
    float ax = fabsf(x), ay = fabsf(y);
    float hi = fmaxf(ax, ay), lo = fminf(ax, ay);
    float t = __fdividef(lo, hi);              // [0,1]
    bool red = t > 0.41421356f;
    float xr = __fdividef(t - 1.0f, t + 1.0f);
    float p = red ? xr : t;
    float z = p * p;
    float poly = fmaf(fmaf(fmaf(fmaf(z, 8.05374449538e-2f, -1.38776856032e-1f), z,
                 1.99777106478e-1f), z, -3.33329491539e-1f), z * p, p);
    float r = red ? (poly + PIO4) : poly;
    r = (ay > ax) ? (PIO2 - r) : r;
    r = (x < 0.0f) ? (PIf - r) : r;
    return copysignf(r, y);
}

// branchless asin, err ~1e-6 rad
__device__ __forceinline__ float fast_asin(float x) {
    float a = fabsf(x);
    bool big = a > 0.5f;
    float zb = 0.5f * (1.0f - a);
    float z = big ? zb : a*a;
    float arg = big ? sqrtf(zb) : a;
    float p = arg * fmaf(z, fmaf(z, fmaf(z, fmaf(z, fmaf(z, fmaf(z,
              1.7352764e-2f, 2.2372159e-2f), 3.0381944e-2f), 4.4642857e-2f),
              7.5e-2f), 1.6666667e-1f), 1.0f);
    float r = big ? fmaf(-2.0f, p, PIO2) : p;
    return copysignf(r, x);
}

// ---------------------------------------------------------------------------
// Kernel D1: departure point + bicubic sample + depthwise scale.
// grid: (ceil(W/256), Bn*NVn*Hn); thread = one (plane, h, w). Low regs, high
// occupancy; all 16 taps proven in-bounds.
// ---------------------------------------------------------------------------
__global__ void kD1_sample(const float* __restrict__ U,
                           const float* __restrict__ Vf,
                           const float* __restrict__ dtp,
                           const float* __restrict__ latg,
                           const float* __restrict__ lonp,
                           const float* __restrict__ dww,
                           const float* __restrict__ dwb) {
    int w = blockIdx.x * blockDim.x + threadIdx.x;
    if (w >= Wn) return;
    int py = blockIdx.y;
    int plane = py / Hn;
    int h = py - plane*Hn;
    int v = plane & (NVn - 1);

    float dt = __ldg(dtp);
    float minLat = __ldg(latg);
    float maxLat = __ldg(latg + (size_t)(Hn-1)*Wn);
    float minLon = __ldg(lonp);
    float maxLon = __ldg(lonp + (Wn-1));
    float dLatInv = 1.0f / (maxLat - minLat);
    float dLonInv = 1.0f / (maxLon - minLon);

    float slg = g_slat[h];
    float clg = g_clat[h];
    float lo  = __ldg(lonp + w);

    size_t base = (size_t)plane*HWn + (size_t)h*Wn + w;
    float uu = U[base];
    float vv = Vf[base];
    float lon_pr = -uu * dt;
    float lat_pr = -vv * dt;
    float slp = sin_sm(lat_pr), clp = cos_sm(lat_pr);
    float sln = sin_sm(lon_pr), cln = cos_sm(lon_pr);

    float sin_lat = fmaf(slp, clg, clp*cln*slg);
    sin_lat = fminf(fmaxf(sin_lat, -1.0f + 1e-7f), 1.0f - 1e-7f);
    float lat_dep = fast_asin(sin_lat);
    float num = clp * sln;
    float den = clp*cln*clg - slp*slg;
    float lon_dep = lo + fast_atan2(num, den);
    float a = lon_dep + TWOPI;
    lon_dep = a - floorf(a * (1.0f/TWOPI)) * TWOPI;   // remainder(a, 2pi)

    float pix_x = (lon_dep - minLon) * dLonInv * (float)(Wn - 1);
    float pix_y = (lat_dep - minLat) * dLatInv * (float)(Hn - 1);
    // normalize/unnormalize round trip (align_corners=True), matches reference fp path
    float gx = 2.0f*((pix_x + (float)PADn)/(float)(Wpn - 1)) - 1.0f;
    float gy = 2.0f*((pix_y + (float)PADn)/(float)(Hpn - 1)) - 1.0f;
    float ix = (gx + 1.0f)*0.5f*(float)(Wpn - 1);
    float iy = (gy + 1.0f)*0.5f*(float)(Hpn - 1);

    float x0f = floorf(ix), y0f = floorf(iy);
    float tx = ix - x0f, ty = iy - y0f;
    int x0 = (int)x0f, y0 = (int)y0f;

    float wx0, wx1, wx2, wx3, wy0, wy1, wy2, wy3;
    {
        float t = tx, t1 = t + 1.0f, t2 = 1.0f - t, t3 = 2.0f - t;
        wx0 = ((ACO*t1 - 5.0f*ACO)*t1 + 8.0f*ACO)*t1 - 4.0f*ACO;
        wx1 = ((ACO + 2.0f)*t - (ACO + 3.0f))*t*t + 1.0f;
        wx2 = ((ACO + 2.0f)*t2 - (ACO + 3.0f))*t2*t2 + 1.0f;
        wx3 = ((ACO*t3 - 5.0f*ACO)*t3 + 8.0f*ACO)*t3 - 4.0f*ACO;
    }
    {
        float t = ty, t1 = t + 1.0f, t2 = 1.0f - t, t3 = 2.0f - t;
        wy0 = ((ACO*t1 - 5.0f*ACO)*t1 + 8.0f*ACO)*t1 - 4.0f*ACO;
        wy1 = ((ACO + 2.0f)*t - (ACO + 3.0f))*t*t + 1.0f;
        wy2 = ((ACO + 2.0f)*t2 - (ACO + 3.0f))*t2*t2 + 1.0f;
        wy3 = ((ACO*t3 - 5.0f*ACO)*t3 + 8.0f*ACO)*t3 - 4.0f*ACO;
    }

    const float* rp = g_pad + (size_t)plane*Hpn*Wpn + (size_t)(y0-1)*Wpn + (x0-1);
    float r0 = fmaf(rp[3], wx3, fmaf(rp[2], wx2, fmaf(rp[1], wx1, rp[0]*wx0)));
    rp += Wpn;
    float r1 = fmaf(rp[3], wx3, fmaf(rp[2], wx2, fmaf(rp[1], wx1, rp[0]*wx0)));
    rp += Wpn;
    float r2 = fmaf(rp[3], wx3, fmaf(rp[2], wx2, fmaf(rp[1], wx1, rp[0]*wx0)));
    rp += Wpn;
    float r3 = fmaf(rp[3], wx3, fmaf(rp[2], wx2, fmaf(rp[1], wx1, rp[0]*wx0)));
    float acc = fmaf(r3, wy3, fmaf(r2, wy2, fmaf(r1, wy1, r0*wy0)));

    g_y[base] = fmaf(acc, __ldg(dww + v), __ldg(dwb + v));
}

// ---------------------------------------------------------------------------
// Kernel D2: up projection (16 -> 128), 2 pixels/thread via packed fp32x2.
// ---------------------------------------------------------------------------
__global__ void kD2_upproj(const float* __restrict__ upw,
                           const float* __restrict__ upb,
                           float* __restrict__ out) {
    __shared__ ull s_w2[HIDn*NVn];   // [o][v], broadcast-packed
    __shared__ float s_b[HIDn];
    for (int i = threadIdx.x; i < HIDn*NVn; i += blockDim.x) {
        float wv = upw[i];
        s_w2[i] = pk2(wv, wv);
    }
    for (int i = threadIdx.x; i < HIDn; i += blockDim.x) s_b[i] = upb[i];
    __syncthreads();

    int idx = blockIdx.x * blockDim.x + threadIdx.x;   // pair index
    if (idx >= Bn*(HWn/2)) return;
    int b = idx / (HWn/2);
    int r = (idx - b*(HWn/2)) * 2;

    ull yv[NVn];
    const float* yp = g_y + (size_t)b*NVn*HWn + r;
#pragma unroll
    for (int vq = 0; vq < NVn; vq++)
        yv[vq] = *reinterpret_cast<const ull*>(yp + (size_t)vq*HWn);

    float* op = out + (size_t)b*HIDn*HWn + r;
#pragma unroll 8
    for (int o = 0; o < HIDn; o++) {
        ull acc = pk2(s_b[o], s_b[o]);
        const ull* wr = s_w2 + o*NVn;
#pragma unroll
        for (int vq = 0; vq < NVn; vq++) acc = ffma2(yv[vq], wr[vq], acc);
        *reinterpret_cast<ull*>(op + (size_t)o*HWn) = acc;
    }
}

// ---------------------------------------------------------------------------
// Kernel E: pole-row fix on output.
// ---------------------------------------------------------------------------
__global__ void kE_polefix_out(float* __restrict__ out) {
    int bo = blockIdx.x >> 1;
    int which = blockIdx.x & 1;
    float* row = out + (size_t)bo*HWn + (which ? (size_t)(Hn-1)*Wn : 0);

    __shared__ float s[256];
    float sum = 0.f;
    for (int w = threadIdx.x; w < Wn; w += 256) sum += row[w];
    s[threadIdx.x] = sum;
    __syncthreads();
    for (int st = 128; st > 0; st >>= 1) {
        if (threadIdx.x < st) s[threadIdx.x] += s[threadIdx.x + st];
        __syncthreads();
    }
    float mean = s[0] * (1.0f / (float)Wn);
    for (int w = threadIdx.x; w < Wn; w += 256) row[w] = mean;
}

// ---------------------------------------------------------------------------
extern "C" void kernel_launch(void* const* d_in, const int* in_sizes, int n_in,
                              void* d_out, int out_size) {
    const float* hidden = (const float*)d_in[0];
    const float* U      = (const float*)d_in[1];
    const float* V      = (const float*)d_in[2];
    const float* dt     = (const float*)d_in[3];
    const float* latg   = (const float*)d_in[4];
    const float* lonog  = (const float*)d_in[5];
    const float* down_w = (const float*)d_in[6];
    const float* down_b = (const float*)d_in[7];
    const float* dw_w   = (const float*)d_in[8];
    const float* dw_b   = (const float*)d_in[9];
    const float* up_w   = (const float*)d_in[10];
    const float* up_b   = (const float*)d_in[11];
    float* out = (float*)d_out;

    int nPairs = Bn*(HWn/2);                 // 259920
    kA_downproj<<<(nPairs + 255)/256, 256>>>(hidden, down_w, down_b);   // 0
    kP_pole_tables<<<4, 256>>>(hidden, down_w, down_b, latg);           // 1
    int nHalo = Bn*NVn*HALO_PER_PLANE;       // 138,880
    kC_halo<<<(nHalo + 255)/256, 256>>>();                              // 2
    dim3 gD1((Wn + 255)/256, Bn*NVn*Hn);
    kD1_sample<<<gD1, 256>>>(U, V, dt, latg, lonog, dw_w, dw_b);        // 3 (profiled)
    kD2_upproj<<<(nPairs + 255)/256, 256>>>(up_w, up_b, out);           // 4
    kE_polefix_out<<<Bn*HIDn*2, 256>>>(out);                            // 5
}